// round 11
// baseline (speedup 1.0000x reference)
#include <cuda_runtime.h>
#include <cuda_fp16.h>
#include <cuda_bf16.h>

#define N_NODES 100000
#define IN_DIM  256
#define HID     128
#define OUT_DIM 32
#define E_MAX   1600000

// ---------------- device scratch ----------------
__device__ __half g_h0h[(size_t)N_NODES * HID];       // fp16 x@W1+b1
__device__ __half g_h1h[(size_t)N_NODES * HID];       // fp16 relu(A@h0)
__device__ __half g_h2h[(size_t)N_NODES * OUT_DIM];   // fp16 h1@W2+b2
__device__ int   g_cnt[N_NODES];                      // zero at entry (rotated)
__device__ int   g_rowptr[N_NODES + 1];
__device__ int   g_cur[N_NODES];
__device__ int   g_bsum[128];
__device__ int2  g_cedge[E_MAX];                      // packed {col, val_bits}

// ---------------------------------------------------------------------------
// mma helpers
// ---------------------------------------------------------------------------
__device__ __forceinline__ unsigned f2tf32(float f) {
    unsigned u;
    asm("cvt.rna.tf32.f32 %0, %1;" : "=r"(u) : "f"(f));
    return u;
}

__device__ __forceinline__ void mma_tf32(float* d, const unsigned* a, const unsigned* b) {
    asm volatile(
        "mma.sync.aligned.m16n8k8.row.col.f32.tf32.tf32.f32 "
        "{%0,%1,%2,%3}, {%4,%5,%6,%7}, {%8,%9}, {%0,%1,%2,%3};\n"
        : "+f"(d[0]), "+f"(d[1]), "+f"(d[2]), "+f"(d[3])
        : "r"(a[0]), "r"(a[1]), "r"(a[2]), "r"(a[3]), "r"(b[0]), "r"(b[1]));
}

__device__ __forceinline__ void mma_f16(float* d, const unsigned* a, const unsigned* b) {
    asm volatile(
        "mma.sync.aligned.m16n8k16.row.col.f32.f16.f16.f32 "
        "{%0,%1,%2,%3}, {%4,%5,%6,%7}, {%8,%9}, {%0,%1,%2,%3};\n"
        : "+f"(d[0]), "+f"(d[1]), "+f"(d[2]), "+f"(d[3])
        : "r"(a[0]), "r"(a[1]), "r"(a[2]), "r"(a[3]), "r"(b[0]), "r"(b[1]));
}

__device__ __forceinline__ void cp_async16(void* smem_dst, const void* gsrc, int src_bytes) {
    unsigned saddr = (unsigned)__cvta_generic_to_shared(smem_dst);
    asm volatile("cp.async.cg.shared.global [%0], [%1], 16, %2;\n"
                 :: "r"(saddr), "l"(gsrc), "r"(src_bytes));
}
__device__ __forceinline__ void cp_async_commit() { asm volatile("cp.async.commit_group;\n"); }
__device__ __forceinline__ void cp_async_wait1()  { asm volatile("cp.async.wait_group 1;\n"); }
__device__ __forceinline__ void cp_async_wait0()  { asm volatile("cp.async.wait_group 0;\n"); }

// ---------------------------------------------------------------------------
// GEMM1 (tf32 mma, cp.async double-buffered): g_h0h = half(x @ W1 + b1)
// cvt.rna.tf32 at fragment load (RNA rounding -> unbiased; keeps rel_err low).
// ---------------------------------------------------------------------------
#define BK2 16
#define NITER (IN_DIM / BK2)
__global__ __launch_bounds__(256) void gemm1_mma_kernel(const float* __restrict__ X,
                                                        const float* __restrict__ W,
                                                        const float* __restrict__ bias) {
    __shared__ float As[2][128][BK2 + 4];
    __shared__ float Bs[2][BK2][HID + 8];

    const int tid  = threadIdx.x;
    const int wid  = tid >> 5;
    const int lane = tid & 31;
    const int g    = lane >> 2;
    const int t    = lane & 3;
    const int wm   = wid >> 2;
    const int wn   = wid & 3;
    const int block_m = blockIdx.x * 128;

    float acc[4][4][4];
#pragma unroll
    for (int mi = 0; mi < 4; mi++)
#pragma unroll
        for (int ni = 0; ni < 4; ni++)
#pragma unroll
            for (int q = 0; q < 4; q++) acc[mi][ni][q] = 0.0f;

    const int ac0_row = tid >> 2;
    const int ac0_col = (tid & 3) * 4;
    const int ac1_row = (tid + 256) >> 2;
    const int ac1_col = ((tid + 256) & 3) * 4;
    const int bc0_row = tid >> 5;
    const int bc0_col = (tid & 31) * 4;
    const int bc1_row = (tid + 256) >> 5;
    const int bc1_col = ((tid + 256) & 31) * 4;

    auto load_stage = [&](int s, int k0) {
        {
            int m = block_m + ac0_row;
            const float* src = X + (size_t)(m < N_NODES ? m : 0) * IN_DIM + k0 + ac0_col;
            cp_async16(&As[s][ac0_row][ac0_col], src, (m < N_NODES) ? 16 : 0);
        }
        {
            int m = block_m + ac1_row;
            const float* src = X + (size_t)(m < N_NODES ? m : 0) * IN_DIM + k0 + ac1_col;
            cp_async16(&As[s][ac1_row][ac1_col], src, (m < N_NODES) ? 16 : 0);
        }
        cp_async16(&Bs[s][bc0_row][bc0_col],
                   W + (size_t)(k0 + bc0_row) * HID + bc0_col, 16);
        cp_async16(&Bs[s][bc1_row][bc1_col],
                   W + (size_t)(k0 + bc1_row) * HID + bc1_col, 16);
    };

    load_stage(0, 0);
    cp_async_commit();

    for (int it = 0; it < NITER; it++) {
        const int s = it & 1;
        if (it + 1 < NITER) {
            load_stage((it + 1) & 1, (it + 1) * BK2);
            cp_async_commit();
            cp_async_wait1();
        } else {
            cp_async_wait0();
        }
        __syncthreads();

#pragma unroll
        for (int kk = 0; kk < BK2; kk += 8) {
            unsigned af[4][4];
            unsigned bf[4][2];
#pragma unroll
            for (int mi = 0; mi < 4; mi++) {
                int m = wm * 64 + mi * 16 + g;
                af[mi][0] = f2tf32(As[s][m][kk + t]);
                af[mi][1] = f2tf32(As[s][m + 8][kk + t]);
                af[mi][2] = f2tf32(As[s][m][kk + t + 4]);
                af[mi][3] = f2tf32(As[s][m + 8][kk + t + 4]);
            }
#pragma unroll
            for (int ni = 0; ni < 4; ni++) {
                int n = wn * 32 + ni * 8 + g;
                bf[ni][0] = f2tf32(Bs[s][kk + t][n]);
                bf[ni][1] = f2tf32(Bs[s][kk + t + 4][n]);
            }
#pragma unroll
            for (int mi = 0; mi < 4; mi++)
#pragma unroll
                for (int ni = 0; ni < 4; ni++)
                    mma_tf32(acc[mi][ni], af[mi], bf[ni]);
        }
        __syncthreads();
    }

#pragma unroll
    for (int ni = 0; ni < 4; ni++) {
        int n = wn * 32 + ni * 8 + 2 * t;
        float b0 = bias[n], b1 = bias[n + 1];
#pragma unroll
        for (int mi = 0; mi < 4; mi++) {
            int r0 = block_m + wm * 64 + mi * 16 + g;
            int r1 = r0 + 8;
            if (r0 < N_NODES)
                *(__half2*)(g_h0h + (size_t)r0 * HID + n) =
                    __floats2half2_rn(acc[mi][ni][0] + b0, acc[mi][ni][1] + b1);
            if (r1 < N_NODES)
                *(__half2*)(g_h0h + (size_t)r1 * HID + n) =
                    __floats2half2_rn(acc[mi][ni][2] + b0, acc[mi][ni][3] + b1);
        }
    }
}

// ---------------------------------------------------------------------------
// CSR build.  g_cnt zero on entry (static init first call; re-zeroed by scan23).
// count/scatter: 4 edges per thread (vector loads, independent atomic chains).
// ---------------------------------------------------------------------------
__global__ void csr_count_kernel(const int* __restrict__ erow, int E) {
    int e4 = blockIdx.x * 256 + threadIdx.x;
    int base = e4 * 4;
    if (base + 3 < E) {
        int4 r = ((const int4*)erow)[e4];
        atomicAdd(&g_cnt[r.x], 1);
        atomicAdd(&g_cnt[r.y], 1);
        atomicAdd(&g_cnt[r.z], 1);
        atomicAdd(&g_cnt[r.w], 1);
    } else {
        for (int e = base; e < E; e++) atomicAdd(&g_cnt[erow[e]], 1);
    }
}

__global__ __launch_bounds__(1024) void scan1_kernel() {
    __shared__ int s[1024];
    int t = threadIdx.x;
    int i = blockIdx.x * 1024 + t;
    int v = (i < N_NODES) ? g_cnt[i] : 0;
    s[t] = v;
    for (int off = 1; off < 1024; off <<= 1) {
        __syncthreads();
        int tmp = (t >= off) ? s[t - off] : 0;
        __syncthreads();
        s[t] += tmp;
    }
    if (i < N_NODES) g_rowptr[i] = s[t] - v;
    if (t == 1023) g_bsum[blockIdx.x] = s[1023];
}

// merged scan2+scan3: each block redundantly scans <=128 block sums in smem,
// applies the offset to its node range, initializes g_cur, re-zeroes g_cnt.
__global__ void scan23_kernel(int nb, int E) {
    __shared__ int s[128];
    int t = threadIdx.x;
    int v = (t < 128) ? ((t < nb) ? g_bsum[t] : 0) : 0;
    if (t < 128) s[t] = v;
    __syncthreads();
    for (int off = 1; off < 128; off <<= 1) {
        int tmp = (t < 128 && t >= off) ? s[t - off] : 0;
        __syncthreads();
        if (t < 128) s[t] += tmp;
        __syncthreads();
    }
    int blk = (int)(blockIdx.x >> 2);            // 256-node block -> 1024-chunk id
    int offset = (blk > 0) ? s[blk - 1] : 0;     // exclusive prefix
    int i = blockIdx.x * 256 + t;
    if (i < N_NODES) {
        int val = g_rowptr[i] + offset;
        g_rowptr[i] = val;
        g_cur[i] = val;
        g_cnt[i] = 0;                            // re-zero for next launch
    }
    if (blockIdx.x == 0 && t == 0) g_rowptr[N_NODES] = E;
}

__global__ void csr_scatter_kernel(const int* __restrict__ erow,
                                   const int* __restrict__ ecol,
                                   const float* __restrict__ eval, int E) {
    int e4 = blockIdx.x * 256 + threadIdx.x;
    int base = e4 * 4;
    if (base + 3 < E) {
        int4   r = ((const int4*)erow)[e4];
        int4   c = ((const int4*)ecol)[e4];
        float4 v = ((const float4*)eval)[e4];
        int i0 = atomicAdd(&g_cur[r.x], 1);
        int i1 = atomicAdd(&g_cur[r.y], 1);
        int i2 = atomicAdd(&g_cur[r.z], 1);
        int i3 = atomicAdd(&g_cur[r.w], 1);
        g_cedge[i0] = make_int2(c.x, __float_as_int(v.x));
        g_cedge[i1] = make_int2(c.y, __float_as_int(v.y));
        g_cedge[i2] = make_int2(c.z, __float_as_int(v.z));
        g_cedge[i3] = make_int2(c.w, __float_as_int(v.w));
    } else {
        for (int e = base; e < E; e++) {
            int idx = atomicAdd(&g_cur[erow[e]], 1);
            g_cedge[idx] = make_int2(ecol[e], __float_as_int(eval[e]));
        }
    }
}

// ---------------------------------------------------------------------------
// SpMM1 + ReLU: g_h1h[r] = relu(sum_e val * g_h0h[col]).  One warp per row;
// 32 lanes x uint2 (4 halves), 8 edges unrolled -> MLP 8; all convergent.
// ---------------------------------------------------------------------------
__global__ __launch_bounds__(256) void spmm1_kernel() {
    const int wid  = threadIdx.x >> 5;
    const int lane = threadIdx.x & 31;
    const int r = blockIdx.x * 8 + wid;
    if (r >= N_NODES) return;

    const int s0 = g_rowptr[r];
    const int s1 = g_rowptr[r + 1];

    float acc[4];
#pragma unroll
    for (int i = 0; i < 4; i++) acc[i] = 0.f;

    for (int base = s0; base < s1; base += 32) {
        int cnt = min(32, s1 - base);
        int2 pk = make_int2(0, 0);
        if (lane < cnt) pk = g_cedge[base + lane];

        int j = 0;
        for (; j + 8 <= cnt; j += 8) {
            int   c[8];
            float v[8];
#pragma unroll
            for (int u = 0; u < 8; u++) {
                c[u] = __shfl_sync(0xffffffffu, pk.x, j + u);
                v[u] = __int_as_float(__shfl_sync(0xffffffffu, pk.y, j + u));
            }
            uint2 hw[8];
#pragma unroll
            for (int u = 0; u < 8; u++)
                hw[u] = ((const uint2*)(g_h0h + (size_t)c[u] * HID))[lane];
#pragma unroll
            for (int u = 0; u < 8; u++) {
                float2 f0 = __half22float2(*(__half2*)&hw[u].x);
                float2 f1 = __half22float2(*(__half2*)&hw[u].y);
                acc[0] += v[u] * f0.x; acc[1] += v[u] * f0.y;
                acc[2] += v[u] * f1.x; acc[3] += v[u] * f1.y;
            }
        }
        for (; j + 4 <= cnt; j += 4) {
            int   c[4];
            float v[4];
#pragma unroll
            for (int u = 0; u < 4; u++) {
                c[u] = __shfl_sync(0xffffffffu, pk.x, j + u);
                v[u] = __int_as_float(__shfl_sync(0xffffffffu, pk.y, j + u));
            }
            uint2 hw[4];
#pragma unroll
            for (int u = 0; u < 4; u++)
                hw[u] = ((const uint2*)(g_h0h + (size_t)c[u] * HID))[lane];
#pragma unroll
            for (int u = 0; u < 4; u++) {
                float2 f0 = __half22float2(*(__half2*)&hw[u].x);
                float2 f1 = __half22float2(*(__half2*)&hw[u].y);
                acc[0] += v[u] * f0.x; acc[1] += v[u] * f0.y;
                acc[2] += v[u] * f1.x; acc[3] += v[u] * f1.y;
            }
        }
        for (; j < cnt; j++) {
            int c = __shfl_sync(0xffffffffu, pk.x, j);
            float v = __int_as_float(__shfl_sync(0xffffffffu, pk.y, j));
            uint2 hw = ((const uint2*)(g_h0h + (size_t)c * HID))[lane];
            float2 f0 = __half22float2(*(__half2*)&hw.x);
            float2 f1 = __half22float2(*(__half2*)&hw.y);
            acc[0] += v * f0.x; acc[1] += v * f0.y;
            acc[2] += v * f1.x; acc[3] += v * f1.y;
        }
    }

    __half2 o0 = __floats2half2_rn(fmaxf(acc[0], 0.f), fmaxf(acc[1], 0.f));
    __half2 o1 = __floats2half2_rn(fmaxf(acc[2], 0.f), fmaxf(acc[3], 0.f));
    uint2 pkout = make_uint2(*(unsigned*)&o0, *(unsigned*)&o1);
    ((uint2*)(g_h1h + (size_t)r * HID))[lane] = pkout;
}

// ---------------------------------------------------------------------------
// GEMM2 (fp16 tensor cores): g_h2h = half(g_h1h @ W2 + b2).
// ---------------------------------------------------------------------------
__global__ __launch_bounds__(256) void gemm2_mma_kernel(const float* __restrict__ W2,
                                                        const float* __restrict__ b2) {
    __shared__ uint2 Bfrag[8][4][32];
    __shared__ float b2s[OUT_DIM];

    const int tid  = threadIdx.x;
    const int wid  = tid >> 5;
    const int lane = tid & 31;
    const int g    = lane >> 2;
    const int t    = lane & 3;

    if (tid < 32) {
#pragma unroll
        for (int ks = 0; ks < 8; ks++)
#pragma unroll
            for (int nf = 0; nf < 4; nf++) {
                int k0 = ks * 16 + 2 * t;
                int n  = nf * 8 + g;
                __half2 lo = __floats2half2_rn(W2[(size_t)k0 * OUT_DIM + n],
                                               W2[(size_t)(k0 + 1) * OUT_DIM + n]);
                __half2 hi = __floats2half2_rn(W2[(size_t)(k0 + 8) * OUT_DIM + n],
                                               W2[(size_t)(k0 + 9) * OUT_DIM + n]);
                Bfrag[ks][nf][lane] = make_uint2(*(unsigned*)&lo, *(unsigned*)&hi);
            }
    }
    if (tid < OUT_DIM) b2s[tid] = b2[tid];
    __syncthreads();

    const int r0 = blockIdx.x * 128 + wid * 16 + g;
    const bool v0 = r0 < N_NODES;
    const bool v1 = (r0 + 8) < N_NODES;
    const unsigned* row0 = (const unsigned*)(g_h1h + (size_t)(v0 ? r0 : 0) * HID);
    const unsigned* row1 = (const unsigned*)(g_h1h + (size_t)(v1 ? r0 + 8 : 0) * HID);

    float acc[4][4];
#pragma unroll
    for (int nf = 0; nf < 4; nf++)
#pragma unroll
        for (int q = 0; q < 4; q++) acc[nf][q] = 0.f;

#pragma unroll
    for (int ks = 0; ks < 8; ks++) {
        const int h = ks * 8 + t;
        unsigned a[4];
        a[0] = v0 ? row0[h] : 0u;
        a[1] = v1 ? row1[h] : 0u;
        a[2] = v0 ? row0[h + 4] : 0u;
        a[3] = v1 ? row1[h + 4] : 0u;
#pragma unroll
        for (int nf = 0; nf < 4; nf++) {
            uint2 b = Bfrag[ks][nf][lane];
            unsigned bb[2] = {b.x, b.y};
            mma_f16(acc[nf], a, bb);
        }
    }

#pragma unroll
    for (int nf = 0; nf < 4; nf++) {
        int n = nf * 8 + 2 * t;
        float bb0 = b2s[n], bb1 = b2s[n + 1];
        if (v0)
            *(__half2*)(g_h2h + (size_t)r0 * OUT_DIM + n) =
                __floats2half2_rn(acc[nf][0] + bb0, acc[nf][1] + bb1);
        if (v1)
            *(__half2*)(g_h2h + (size_t)(r0 + 8) * OUT_DIM + n) =
                __floats2half2_rn(acc[nf][2] + bb0, acc[nf][3] + bb1);
    }
}

// ---------------------------------------------------------------------------
// SpMM2: 16 lanes per row (half2 each); halves process alternating edges,
// 8 edges unrolled per half -> MLP 8.
// ---------------------------------------------------------------------------
__global__ __launch_bounds__(256) void spmm2_csr_kernel(float* __restrict__ out) {
    const int wid  = threadIdx.x >> 5;
    const int lane = threadIdx.x & 31;
    const int half = lane >> 4;
    const int l16  = lane & 15;
    const int r = blockIdx.x * 8 + wid;
    if (r >= N_NODES) return;

    const int s0 = g_rowptr[r];
    const int s1 = g_rowptr[r + 1];

    float2 acc = make_float2(0.f, 0.f);
    for (int base = s0; base < s1; base += 32) {
        int cnt = min(32, s1 - base);
        int2 pk = make_int2(0, 0);
        if (lane < cnt) pk = g_cedge[base + lane];

        int j = 0;
        for (; j + 16 <= cnt; j += 16) {
            int   c[8];
            float v[8];
#pragma unroll
            for (int u = 0; u < 8; u++) {
                int e = j + 2 * u + half;
                c[u] = __shfl_sync(0xffffffffu, pk.x, e);
                v[u] = __int_as_float(__shfl_sync(0xffffffffu, pk.y, e));
            }
            __half2 hv[8];
#pragma unroll
            for (int u = 0; u < 8; u++)
                hv[u] = ((const __half2*)(g_h2h + (size_t)c[u] * OUT_DIM))[l16];
#pragma unroll
            for (int u = 0; u < 8; u++) {
                float2 f = __half22float2(hv[u]);
                acc.x += v[u] * f.x;
                acc.y += v[u] * f.y;
            }
        }
        for (; j < cnt; j += 2) {
            int e = j + half;
            int esafe = (e < cnt) ? e : (cnt - 1);
            int c = __shfl_sync(0xffffffffu, pk.x, esafe);
            float v = __int_as_float(__shfl_sync(0xffffffffu, pk.y, esafe));
            if (e >= cnt) v = 0.f;
            __half2 hv = ((const __half2*)(g_h2h + (size_t)c * OUT_DIM))[l16];
            float2 f = __half22float2(hv);
            acc.x += v * f.x;
            acc.y += v * f.y;
        }
    }

    acc.x += __shfl_xor_sync(0xffffffffu, acc.x, 16);
    acc.y += __shfl_xor_sync(0xffffffffu, acc.y, 16);
    if (half == 0)
        *(float2*)(out + (size_t)r * OUT_DIM + 2 * l16) = acc;
}

// ---------------------------------------------------------------------------
// Launch.  CSR chain on side stream; gemm1 on main.  csr_scatter stays at
// ncu slot #4.
// ---------------------------------------------------------------------------
extern "C" void kernel_launch(void* const* d_in, const int* in_sizes, int n_in,
                              void* d_out, int out_size) {
    const float* x    = (const float*)d_in[0];
    const int*   erow = (const int*)d_in[1];
    const int*   ecol = (const int*)d_in[2];
    const float* eval = (const float*)d_in[3];
    const float* W1   = (const float*)d_in[4];
    const float* b1   = (const float*)d_in[5];
    const float* W2   = (const float*)d_in[6];
    const float* b2   = (const float*)d_in[7];
    float* out = (float*)d_out;
    const int E = in_sizes[1];

    static cudaStream_t s1 = nullptr;
    static cudaEvent_t ev_fork = nullptr, ev_join = nullptr;
    if (s1 == nullptr) {
        cudaStreamCreateWithFlags(&s1, cudaStreamNonBlocking);
        cudaEventCreateWithFlags(&ev_fork, cudaEventDisableTiming);
        cudaEventCreateWithFlags(&ev_join, cudaEventDisableTiming);
    }

    const int nb_nodes  = (N_NODES + 255) / 256;
    const int nb_edges4 = (E / 4 + 255) / 256 + 1;   // 4 edges/thread (+tail block)
    const int nb_scan   = (N_NODES + 1023) / 1024;
    const int nb_rows8  = (N_NODES + 7) / 8;

    cudaEventRecord(ev_fork, 0);
    cudaStreamWaitEvent(s1, ev_fork, 0);

    // CSR chain on s1 (launches 1,2,3,4 — scatter is #4 for ncu)
    csr_count_kernel<<<nb_edges4, 256, 0, s1>>>(erow, E);
    scan1_kernel<<<nb_scan, 1024, 0, s1>>>();
    scan23_kernel<<<nb_nodes, 256, 0, s1>>>(nb_scan, E);
    csr_scatter_kernel<<<nb_edges4, 256, 0, s1>>>(erow, ecol, eval, E);
    cudaEventRecord(ev_join, s1);

    // GEMM1 on main stream
    gemm1_mma_kernel<<<(N_NODES + 127) / 128, 256>>>(x, W1, b1);

    // join, then SpMM1 -> GEMM2 -> SpMM2
    cudaStreamWaitEvent(0, ev_join, 0);
    spmm1_kernel<<<nb_rows8, 256>>>();
    gemm2_mma_kernel<<<(N_NODES + 127) / 128, 256>>>(W2, b2);
    spmm2_csr_kernel<<<nb_rows8, 256>>>(out);
}

// round 12
// speedup vs baseline: 1.0190x; 1.0190x over previous
#include <cuda_runtime.h>
#include <cuda_fp16.h>
#include <cuda_bf16.h>

#define N_NODES 100000
#define IN_DIM  256
#define HID     128
#define OUT_DIM 32
#define E_MAX   1600000

// ---------------- device scratch ----------------
__device__ __half g_h0h[(size_t)N_NODES * HID];       // fp16 x@W1+b1
__device__ __half g_h1h[(size_t)N_NODES * HID];       // fp16 relu(A@h0)
__device__ __half g_h2h[(size_t)N_NODES * OUT_DIM];   // fp16 h1@W2+b2
__device__ int   g_cnt[N_NODES];                      // zero at entry (rotated)
__device__ int   g_rowptr[N_NODES + 1];
__device__ int   g_cur[N_NODES];
__device__ int   g_bsum[128];
__device__ int2  g_cedge[E_MAX];                      // packed {col, val_bits}

// ---------------------------------------------------------------------------
// mma helpers
// ---------------------------------------------------------------------------
__device__ __forceinline__ void mma_f16(float* d, const unsigned* a, const unsigned* b) {
    asm volatile(
        "mma.sync.aligned.m16n8k16.row.col.f32.f16.f16.f32 "
        "{%0,%1,%2,%3}, {%4,%5,%6,%7}, {%8,%9}, {%0,%1,%2,%3};\n"
        : "+f"(d[0]), "+f"(d[1]), "+f"(d[2]), "+f"(d[3])
        : "r"(a[0]), "r"(a[1]), "r"(a[2]), "r"(a[3]), "r"(b[0]), "r"(b[1]));
}

__device__ __forceinline__ unsigned smem_u32(const void* p) {
    return (unsigned)__cvta_generic_to_shared(p);
}

__device__ __forceinline__ void ldmatrix_x4(unsigned* r, unsigned addr) {
    asm volatile("ldmatrix.sync.aligned.m8n8.x4.shared.b16 {%0,%1,%2,%3}, [%4];"
                 : "=r"(r[0]), "=r"(r[1]), "=r"(r[2]), "=r"(r[3]) : "r"(addr));
}

__device__ __forceinline__ void ldmatrix_x2_trans(unsigned* r, unsigned addr) {
    asm volatile("ldmatrix.sync.aligned.m8n8.x2.trans.shared.b16 {%0,%1}, [%2];"
                 : "=r"(r[0]), "=r"(r[1]) : "r"(addr));
}

// ---------------------------------------------------------------------------
// GEMM1 (fp16 tensor cores, ldmatrix, reg-staged double buffer):
//   g_h0h = half(x @ W1 + b1).  M=100000, K=256, N=128.
// fp16 mantissa == tf32 mantissa (11 bits), fp32 accumulate -> same accuracy.
// 128x128 block, BK=16, 256 thr (8 warps 2x4, 64x32/warp), 1 sync/stage.
// ---------------------------------------------------------------------------
#define BKH 16
#define NITERH (IN_DIM / BKH)   // 16
#define A_LD 24                  // halves per Ah row (pad 16->24, 48B, cf-free)
#define B_LD 136                 // halves per Bh row (pad 128->136, 272B, cf-free)

__global__ __launch_bounds__(256) void gemm1_mma_kernel(const float* __restrict__ X,
                                                        const float* __restrict__ W,
                                                        const float* __restrict__ bias) {
    __shared__ __half Ah[2][128][A_LD];   // 12.3 KB
    __shared__ __half Bh[2][BKH][B_LD];   //  8.7 KB

    const int tid  = threadIdx.x;
    const int wid  = tid >> 5;
    const int lane = tid & 31;
    const int g    = lane >> 2;
    const int t    = lane & 3;
    const int wm   = wid >> 2;
    const int wn   = wid & 3;
    const int block_m = blockIdx.x * 128;

    float acc[4][4][4];
#pragma unroll
    for (int mi = 0; mi < 4; mi++)
#pragma unroll
        for (int ni = 0; ni < 4; ni++)
#pragma unroll
            for (int q = 0; q < 4; q++) acc[mi][ni][q] = 0.0f;

    // A ldg map: row = tid>>1 (0..127), 8 k's at (tid&1)*8
    const int ar = tid >> 1;
    const int ak = (tid & 1) * 8;
    const bool avalid = (block_m + ar) < N_NODES;
    const float* aptr = X + (size_t)(avalid ? block_m + ar : 0) * IN_DIM + ak;
    // B ldg map: k = tid>>4 (0..15), 8 n's at (tid&15)*8
    const int bk = tid >> 4;
    const int bn = (tid & 15) * 8;
    const float* bptr = W + (size_t)bk * HID + bn;

    float4 ra0, ra1, rb0, rb1;

    auto ldg_stage = [&](int k0) {
        if (avalid) {
            ra0 = *(const float4*)(aptr + k0);
            ra1 = *(const float4*)(aptr + k0 + 4);
        } else {
            ra0 = make_float4(0.f, 0.f, 0.f, 0.f);
            ra1 = ra0;
        }
        rb0 = *(const float4*)(bptr + (size_t)k0 * HID);
        rb1 = *(const float4*)(bptr + (size_t)k0 * HID + 4);
    };

    auto sts_stage = [&](int s) {
        __half2 ha[4];
        ha[0] = __floats2half2_rn(ra0.x, ra0.y);
        ha[1] = __floats2half2_rn(ra0.z, ra0.w);
        ha[2] = __floats2half2_rn(ra1.x, ra1.y);
        ha[3] = __floats2half2_rn(ra1.z, ra1.w);
        *(uint4*)&Ah[s][ar][ak] = *(uint4*)ha;
        __half2 hb[4];
        hb[0] = __floats2half2_rn(rb0.x, rb0.y);
        hb[1] = __floats2half2_rn(rb0.z, rb0.w);
        hb[2] = __floats2half2_rn(rb1.x, rb1.y);
        hb[3] = __floats2half2_rn(rb1.z, rb1.w);
        *(uint4*)&Bh[s][bk][bn] = *(uint4*)hb;
    };

    // ldmatrix lane addressing (constant across stages)
    const int a_mloc = (lane & 7) + ((lane >> 3) & 1) * 8;   // row within m16 tile pair
    const int a_kloc = ((lane >> 4) & 1) * 8;                // 0 or 8
    const int b_krow = lane & 15;                            // k row for B (x2 uses lanes 0-15)

    ldg_stage(0);
    sts_stage(0);
    __syncthreads();

    for (int it = 0; it < NITERH; it++) {
        const int s = it & 1;
        if (it + 1 < NITERH) ldg_stage((it + 1) * BKH);

        // compute one k16 stage
        unsigned af[4][4];
        unsigned bf[4][2];
#pragma unroll
        for (int mf = 0; mf < 4; mf++) {
            unsigned addr = smem_u32(&Ah[s][wm * 64 + mf * 16 + a_mloc][a_kloc]);
            ldmatrix_x4(af[mf], addr);
        }
#pragma unroll
        for (int nf = 0; nf < 4; nf++) {
            unsigned addr = smem_u32(&Bh[s][b_krow][wn * 32 + nf * 8]);
            ldmatrix_x2_trans(bf[nf], addr);
        }
#pragma unroll
        for (int mf = 0; mf < 4; mf++)
#pragma unroll
            for (int nf = 0; nf < 4; nf++)
                mma_f16(acc[mf][nf], af[mf], bf[nf]);

        if (it + 1 < NITERH) {
            sts_stage(s ^ 1);
            __syncthreads();
        }
    }

    // epilogue: add bias (fp32), store half2
#pragma unroll
    for (int ni = 0; ni < 4; ni++) {
        int n = wn * 32 + ni * 8 + 2 * t;
        float b0 = bias[n], b1 = bias[n + 1];
#pragma unroll
        for (int mi = 0; mi < 4; mi++) {
            int r0 = block_m + wm * 64 + mi * 16 + g;
            int r1 = r0 + 8;
            if (r0 < N_NODES)
                *(__half2*)(g_h0h + (size_t)r0 * HID + n) =
                    __floats2half2_rn(acc[mi][ni][0] + b0, acc[mi][ni][1] + b1);
            if (r1 < N_NODES)
                *(__half2*)(g_h0h + (size_t)r1 * HID + n) =
                    __floats2half2_rn(acc[mi][ni][2] + b0, acc[mi][ni][3] + b1);
        }
    }
}

// ---------------------------------------------------------------------------
// CSR build (scalar count/scatter — measured faster than vectorized).
// g_cnt zero on entry (static init first call; re-zeroed by scan23).
// ---------------------------------------------------------------------------
__global__ void csr_count_kernel(const int* __restrict__ erow, int E) {
    int e = blockIdx.x * 256 + threadIdx.x;
    if (e < E) atomicAdd(&g_cnt[erow[e]], 1);
}

__global__ __launch_bounds__(1024) void scan1_kernel() {
    __shared__ int s[1024];
    int t = threadIdx.x;
    int i = blockIdx.x * 1024 + t;
    int v = (i < N_NODES) ? g_cnt[i] : 0;
    s[t] = v;
    for (int off = 1; off < 1024; off <<= 1) {
        __syncthreads();
        int tmp = (t >= off) ? s[t - off] : 0;
        __syncthreads();
        s[t] += tmp;
    }
    if (i < N_NODES) g_rowptr[i] = s[t] - v;
    if (t == 1023) g_bsum[blockIdx.x] = s[1023];
}

__global__ void scan23_kernel(int nb, int E) {
    __shared__ int s[128];
    int t = threadIdx.x;
    int v = (t < 128) ? ((t < nb) ? g_bsum[t] : 0) : 0;
    if (t < 128) s[t] = v;
    __syncthreads();
    for (int off = 1; off < 128; off <<= 1) {
        int tmp = (t < 128 && t >= off) ? s[t - off] : 0;
        __syncthreads();
        if (t < 128) s[t] += tmp;
        __syncthreads();
    }
    int blk = (int)(blockIdx.x >> 2);
    int offset = (blk > 0) ? s[blk - 1] : 0;
    int i = blockIdx.x * 256 + t;
    if (i < N_NODES) {
        int val = g_rowptr[i] + offset;
        g_rowptr[i] = val;
        g_cur[i] = val;
        g_cnt[i] = 0;
    }
    if (blockIdx.x == 0 && t == 0) g_rowptr[N_NODES] = E;
}

__global__ void csr_scatter_kernel(const int* __restrict__ erow,
                                   const int* __restrict__ ecol,
                                   const float* __restrict__ eval, int E) {
    int e = blockIdx.x * 256 + threadIdx.x;
    if (e < E) {
        int r = erow[e];
        int idx = atomicAdd(&g_cur[r], 1);
        g_cedge[idx] = make_int2(ecol[e], __float_as_int(eval[e]));
    }
}

// ---------------------------------------------------------------------------
// SpMM1 + ReLU: g_h1h[r] = relu(sum_e val * g_h0h[col]).  One warp per row;
// 32 lanes x uint2 (4 halves), 8 edges unrolled -> MLP 8; all convergent.
// ---------------------------------------------------------------------------
__global__ __launch_bounds__(256) void spmm1_kernel() {
    const int wid  = threadIdx.x >> 5;
    const int lane = threadIdx.x & 31;
    const int r = blockIdx.x * 8 + wid;
    if (r >= N_NODES) return;

    const int s0 = g_rowptr[r];
    const int s1 = g_rowptr[r + 1];

    float acc[4];
#pragma unroll
    for (int i = 0; i < 4; i++) acc[i] = 0.f;

    for (int base = s0; base < s1; base += 32) {
        int cnt = min(32, s1 - base);
        int2 pk = make_int2(0, 0);
        if (lane < cnt) pk = g_cedge[base + lane];

        int j = 0;
        for (; j + 8 <= cnt; j += 8) {
            int   c[8];
            float v[8];
#pragma unroll
            for (int u = 0; u < 8; u++) {
                c[u] = __shfl_sync(0xffffffffu, pk.x, j + u);
                v[u] = __int_as_float(__shfl_sync(0xffffffffu, pk.y, j + u));
            }
            uint2 hw[8];
#pragma unroll
            for (int u = 0; u < 8; u++)
                hw[u] = ((const uint2*)(g_h0h + (size_t)c[u] * HID))[lane];
#pragma unroll
            for (int u = 0; u < 8; u++) {
                float2 f0 = __half22float2(*(__half2*)&hw[u].x);
                float2 f1 = __half22float2(*(__half2*)&hw[u].y);
                acc[0] += v[u] * f0.x; acc[1] += v[u] * f0.y;
                acc[2] += v[u] * f1.x; acc[3] += v[u] * f1.y;
            }
        }
        for (; j + 4 <= cnt; j += 4) {
            int   c[4];
            float v[4];
#pragma unroll
            for (int u = 0; u < 4; u++) {
                c[u] = __shfl_sync(0xffffffffu, pk.x, j + u);
                v[u] = __int_as_float(__shfl_sync(0xffffffffu, pk.y, j + u));
            }
            uint2 hw[4];
#pragma unroll
            for (int u = 0; u < 4; u++)
                hw[u] = ((const uint2*)(g_h0h + (size_t)c[u] * HID))[lane];
#pragma unroll
            for (int u = 0; u < 4; u++) {
                float2 f0 = __half22float2(*(__half2*)&hw[u].x);
                float2 f1 = __half22float2(*(__half2*)&hw[u].y);
                acc[0] += v[u] * f0.x; acc[1] += v[u] * f0.y;
                acc[2] += v[u] * f1.x; acc[3] += v[u] * f1.y;
            }
        }
        for (; j < cnt; j++) {
            int c = __shfl_sync(0xffffffffu, pk.x, j);
            float v = __int_as_float(__shfl_sync(0xffffffffu, pk.y, j));
            uint2 hw = ((const uint2*)(g_h0h + (size_t)c * HID))[lane];
            float2 f0 = __half22float2(*(__half2*)&hw.x);
            float2 f1 = __half22float2(*(__half2*)&hw.y);
            acc[0] += v * f0.x; acc[1] += v * f0.y;
            acc[2] += v * f1.x; acc[3] += v * f1.y;
        }
    }

    __half2 o0 = __floats2half2_rn(fmaxf(acc[0], 0.f), fmaxf(acc[1], 0.f));
    __half2 o1 = __floats2half2_rn(fmaxf(acc[2], 0.f), fmaxf(acc[3], 0.f));
    uint2 pkout = make_uint2(*(unsigned*)&o0, *(unsigned*)&o1);
    ((uint2*)(g_h1h + (size_t)r * HID))[lane] = pkout;
}

// ---------------------------------------------------------------------------
// GEMM2 (fp16 tensor cores): g_h2h = half(g_h1h @ W2 + b2).
// ---------------------------------------------------------------------------
__global__ __launch_bounds__(256) void gemm2_mma_kernel(const float* __restrict__ W2,
                                                        const float* __restrict__ b2) {
    __shared__ uint2 Bfrag[8][4][32];
    __shared__ float b2s[OUT_DIM];

    const int tid  = threadIdx.x;
    const int wid  = tid >> 5;
    const int lane = tid & 31;
    const int g    = lane >> 2;
    const int t    = lane & 3;

    if (tid < 32) {
#pragma unroll
        for (int ks = 0; ks < 8; ks++)
#pragma unroll
            for (int nf = 0; nf < 4; nf++) {
                int k0 = ks * 16 + 2 * t;
                int n  = nf * 8 + g;
                __half2 lo = __floats2half2_rn(W2[(size_t)k0 * OUT_DIM + n],
                                               W2[(size_t)(k0 + 1) * OUT_DIM + n]);
                __half2 hi = __floats2half2_rn(W2[(size_t)(k0 + 8) * OUT_DIM + n],
                                               W2[(size_t)(k0 + 9) * OUT_DIM + n]);
                Bfrag[ks][nf][lane] = make_uint2(*(unsigned*)&lo, *(unsigned*)&hi);
            }
    }
    if (tid < OUT_DIM) b2s[tid] = b2[tid];
    __syncthreads();

    const int r0 = blockIdx.x * 128 + wid * 16 + g;
    const bool v0 = r0 < N_NODES;
    const bool v1 = (r0 + 8) < N_NODES;
    const unsigned* row0 = (const unsigned*)(g_h1h + (size_t)(v0 ? r0 : 0) * HID);
    const unsigned* row1 = (const unsigned*)(g_h1h + (size_t)(v1 ? r0 + 8 : 0) * HID);

    float acc[4][4];
#pragma unroll
    for (int nf = 0; nf < 4; nf++)
#pragma unroll
        for (int q = 0; q < 4; q++) acc[nf][q] = 0.f;

#pragma unroll
    for (int ks = 0; ks < 8; ks++) {
        const int h = ks * 8 + t;
        unsigned a[4];
        a[0] = v0 ? row0[h] : 0u;
        a[1] = v1 ? row1[h] : 0u;
        a[2] = v0 ? row0[h + 4] : 0u;
        a[3] = v1 ? row1[h + 4] : 0u;
#pragma unroll
        for (int nf = 0; nf < 4; nf++) {
            uint2 b = Bfrag[ks][nf][lane];
            unsigned bb[2] = {b.x, b.y};
            mma_f16(acc[nf], a, bb);
        }
    }

#pragma unroll
    for (int nf = 0; nf < 4; nf++) {
        int n = nf * 8 + 2 * t;
        float bb0 = b2s[n], bb1 = b2s[n + 1];
        if (v0)
            *(__half2*)(g_h2h + (size_t)r0 * OUT_DIM + n) =
                __floats2half2_rn(acc[nf][0] + bb0, acc[nf][1] + bb1);
        if (v1)
            *(__half2*)(g_h2h + (size_t)(r0 + 8) * OUT_DIM + n) =
                __floats2half2_rn(acc[nf][2] + bb0, acc[nf][3] + bb1);
    }
}

// ---------------------------------------------------------------------------
// SpMM2: 16 lanes per row (half2 each); halves process alternating edges,
// 8 edges unrolled per half -> MLP 8.
// ---------------------------------------------------------------------------
__global__ __launch_bounds__(256) void spmm2_csr_kernel(float* __restrict__ out) {
    const int wid  = threadIdx.x >> 5;
    const int lane = threadIdx.x & 31;
    const int half = lane >> 4;
    const int l16  = lane & 15;
    const int r = blockIdx.x * 8 + wid;
    if (r >= N_NODES) return;

    const int s0 = g_rowptr[r];
    const int s1 = g_rowptr[r + 1];

    float2 acc = make_float2(0.f, 0.f);
    for (int base = s0; base < s1; base += 32) {
        int cnt = min(32, s1 - base);
        int2 pk = make_int2(0, 0);
        if (lane < cnt) pk = g_cedge[base + lane];

        int j = 0;
        for (; j + 16 <= cnt; j += 16) {
            int   c[8];
            float v[8];
#pragma unroll
            for (int u = 0; u < 8; u++) {
                int e = j + 2 * u + half;
                c[u] = __shfl_sync(0xffffffffu, pk.x, e);
                v[u] = __int_as_float(__shfl_sync(0xffffffffu, pk.y, e));
            }
            __half2 hv[8];
#pragma unroll
            for (int u = 0; u < 8; u++)
                hv[u] = ((const __half2*)(g_h2h + (size_t)c[u] * OUT_DIM))[l16];
#pragma unroll
            for (int u = 0; u < 8; u++) {
                float2 f = __half22float2(hv[u]);
                acc.x += v[u] * f.x;
                acc.y += v[u] * f.y;
            }
        }
        for (; j < cnt; j += 2) {
            int e = j + half;
            int esafe = (e < cnt) ? e : (cnt - 1);
            int c = __shfl_sync(0xffffffffu, pk.x, esafe);
            float v = __int_as_float(__shfl_sync(0xffffffffu, pk.y, esafe));
            if (e >= cnt) v = 0.f;
            __half2 hv = ((const __half2*)(g_h2h + (size_t)c * OUT_DIM))[l16];
            float2 f = __half22float2(hv);
            acc.x += v * f.x;
            acc.y += v * f.y;
        }
    }

    acc.x += __shfl_xor_sync(0xffffffffu, acc.x, 16);
    acc.y += __shfl_xor_sync(0xffffffffu, acc.y, 16);
    if (half == 0)
        *(float2*)(out + (size_t)r * OUT_DIM + 2 * l16) = acc;
}

// ---------------------------------------------------------------------------
// Launch.  CSR chain on side stream; gemm1 on main; scatter at ncu slot #4.
// ---------------------------------------------------------------------------
extern "C" void kernel_launch(void* const* d_in, const int* in_sizes, int n_in,
                              void* d_out, int out_size) {
    const float* x    = (const float*)d_in[0];
    const int*   erow = (const int*)d_in[1];
    const int*   ecol = (const int*)d_in[2];
    const float* eval = (const float*)d_in[3];
    const float* W1   = (const float*)d_in[4];
    const float* b1   = (const float*)d_in[5];
    const float* W2   = (const float*)d_in[6];
    const float* b2   = (const float*)d_in[7];
    float* out = (float*)d_out;
    const int E = in_sizes[1];

    static cudaStream_t s1 = nullptr;
    static cudaEvent_t ev_fork = nullptr, ev_join = nullptr;
    if (s1 == nullptr) {
        cudaStreamCreateWithFlags(&s1, cudaStreamNonBlocking);
        cudaEventCreateWithFlags(&ev_fork, cudaEventDisableTiming);
        cudaEventCreateWithFlags(&ev_join, cudaEventDisableTiming);
    }

    const int nb_nodes = (N_NODES + 255) / 256;
    const int nb_edges = (E + 255) / 256;
    const int nb_scan  = (N_NODES + 1023) / 1024;
    const int nb_rows8 = (N_NODES + 7) / 8;

    cudaEventRecord(ev_fork, 0);
    cudaStreamWaitEvent(s1, ev_fork, 0);

    // CSR chain on s1 (launches 1,2,3,4 — scatter is #4 for ncu)
    csr_count_kernel<<<nb_edges, 256, 0, s1>>>(erow, E);
    scan1_kernel<<<nb_scan, 1024, 0, s1>>>();
    scan23_kernel<<<nb_nodes, 256, 0, s1>>>(nb_scan, E);
    csr_scatter_kernel<<<nb_edges, 256, 0, s1>>>(erow, ecol, eval, E);
    cudaEventRecord(ev_join, s1);

    // GEMM1 (fp16/ldmatrix) on main stream
    gemm1_mma_kernel<<<(N_NODES + 127) / 128, 256>>>(x, W1, b1);

    // join, then SpMM1 -> GEMM2 -> SpMM2
    cudaStreamWaitEvent(0, ev_join, 0);
    spmm1_kernel<<<nb_rows8, 256>>>();
    gemm2_mma_kernel<<<(N_NODES + 127) / 128, 256>>>(W2, b2);
    spmm2_csr_kernel<<<nb_rows8, 256>>>(out);
}